// round 15
// baseline (speedup 1.0000x reference)
#include <cuda_runtime.h>
#include <cuda_fp16.h>
#include <cstdint>

#define N_PTS 16384
#define C_DIM 64
#define NFRAG (N_PTS / 16 * 4 * 32)   // 131072 uint4 fragments
#define JSPLIT 16

// ---------------- scratch (no allocs allowed) ----------------
__device__ uint32_t g_iext[N_PTS * 8];        // A-side feats [r0..r4,1,0,0] tf32 bits
__device__ float    g_h[N_PTS];               // exact fp32 h_i
__device__ float2   g_jext2[N_PTS * 4];       // score-mma B frags {(f0,f4),(f1,h),(f2,0),(f3,0)}
__device__ uint4    g_Ufrag[NFRAG];           // U fp16, HMMA-B fragment order
__device__ float    g_part[JSPLIT * N_PTS * C_DIM]; // split-j partials

__device__ __forceinline__ uint32_t tf32r(float v) {
    uint32_t u; asm("cvt.rna.tf32.f32 %0, %1;" : "=r"(u) : "f"(v)); return u;
}

// ---------------- fused prep: features + U fragments ----------------
__global__ void prep_all(const float* __restrict__ ref, const float* __restrict__ U) {
    int idx = blockIdx.x * blockDim.x + threadIdx.x;

    if (idx < N_PTS) {
        const int p = idx;
        const float L2E = 1.4426950408889634f;
        const float S   = 1.2011224087864498f;   // sqrt(log2 e)
        float r[5]; float sq = 0.f;
        #pragma unroll
        for (int c = 0; c < 5; c++) { r[c] = ref[p * 5 + c]; sq += r[c] * r[c]; }
        float h = -0.5f * L2E * sq;
        uint32_t f[6];
        #pragma unroll
        for (int c = 0; c < 5; c++) f[c] = tf32r(r[c] * S);
        f[5] = tf32r(h);
        uint32_t* ie = g_iext + (size_t)p * 8;
        ie[0] = f[0]; ie[1] = f[1]; ie[2] = f[2]; ie[3] = f[3]; ie[4] = f[4];
        ie[5] = tf32r(1.0f); ie[6] = 0u; ie[7] = 0u;
        g_h[p] = h;
        float2* je = g_jext2 + (size_t)p * 4;
        je[0] = make_float2(__uint_as_float(f[0]), __uint_as_float(f[4]));
        je[1] = make_float2(__uint_as_float(f[1]), __uint_as_float(f[5]));
        je[2] = make_float2(__uint_as_float(f[2]), 0.f);
        je[3] = make_float2(__uint_as_float(f[3]), 0.f);
    }

    if (idx < NFRAG) {
        int lane = idx & 31, nbp = (idx >> 5) & 3, J = idx >> 7;
        int qr = lane >> 2, qc = lane & 3;
        int j = J * 16 + 2 * qc;
        uint32_t rr[4];
        #pragma unroll
        for (int p = 0; p < 2; p++) {
            int c = (2 * nbp + p) * 8 + qr;
            float f0 = U[(size_t)j * C_DIM + c];
            float f1 = U[(size_t)(j + 1) * C_DIM + c];
            float f2 = U[(size_t)(j + 8) * C_DIM + c];
            float f3 = U[(size_t)(j + 9) * C_DIM + c];
            __half2 h0 = __floats2half2_rn(f0, f1);   // lo = row 2qc
            __half2 h1 = __floats2half2_rn(f2, f3);
            rr[2 * p]     = *(uint32_t*)&h0;
            rr[2 * p + 1] = *(uint32_t*)&h1;
        }
        g_Ufrag[idx] = make_uint4(rr[0], rr[1], rr[2], rr[3]);
    }
}

// ---------------- main kernel pieces ----------------
// score MMA with h preloaded in the accumulator: c = {h0,h0,h1,h1} + A.B
__device__ __forceinline__ void score_mma_h(
    float c[4],
    uint32_t ia0, uint32_t ia1, uint32_t ia2, uint32_t ia3, float2 bf,
    float h0, float h1)
{
    uint32_t b0 = __float_as_uint(bf.x), b1 = __float_as_uint(bf.y);
    c[0] = h0; c[1] = h0; c[2] = h1; c[3] = h1;
    asm volatile("mma.sync.aligned.m16n8k8.row.col.f32.tf32.tf32.f32 "
                 "{%0,%1,%2,%3}, {%4,%5,%6,%7}, {%8,%9}, {%0,%1,%2,%3};"
                 : "+f"(c[0]), "+f"(c[1]), "+f"(c[2]), "+f"(c[3])
                 : "r"(ia0), "r"(ia1), "r"(ia2), "r"(ia3), "r"(b0), "r"(b1));
}

// finalize: e already includes h; clamp + exp2 + pack to f16x2
__device__ __forceinline__ void finalize(
    uint32_t& w_lo, uint32_t& w_hi, const float c[4])
{
    uint32_t plo, phi;
    asm("cvt.rn.f16x2.f32 %0, %1, %2;" : "=r"(plo) : "f"(c[1]), "f"(c[0])); // lo=c0
    asm("cvt.rn.f16x2.f32 %0, %1, %2;" : "=r"(phi) : "f"(c[3]), "f"(c[2]));
    asm("min.f16x2 %0, %1, %2;" : "=r"(plo) : "r"(plo), "r"(0u));
    asm("min.f16x2 %0, %1, %2;" : "=r"(phi) : "r"(phi), "r"(0u));
    asm("ex2.approx.f16x2 %0, %1;" : "=r"(w_lo) : "r"(plo));
    asm("ex2.approx.f16x2 %0, %1;" : "=r"(w_hi) : "r"(phi));
}

#define HMMA(ACC, A0, A1, A2, A3, B0, B1) \
    asm volatile("mma.sync.aligned.m16n8k16.row.col.f32.f16.f16.f32 " \
                 "{%0,%1,%2,%3}, {%4,%5,%6,%7}, {%8,%9}, {%0,%1,%2,%3};" \
                 : "+f"(ACC[0]), "+f"(ACC[1]), "+f"(ACC[2]), "+f"(ACC[3]) \
                 : "r"(A0), "r"(A1), "r"(A2), "r"(A3), "r"(B0), "r"(B1))

__global__ void __launch_bounds__(128, 6)
lsh_main(void) {
    const int lane = threadIdx.x & 31;
    const int w    = threadIdx.x >> 5;          // 0..3: m16 tile within 64-row i-tile
    const int bid  = blockIdx.x;
    const int ib   = bid & 255;                 // i-tile (64 rows)
    const int jh   = bid >> 8;                  // j-slice 0..15
    const int i0   = ib * 64;
    const int qr   = lane >> 2, qc = lane & 3;

    // this warp's m16 rows: ri (a0/a2), ri+8 (a1/a3)
    const int ri = i0 + w * 16 + qr;
    const uint32_t ia0 = g_iext[(size_t)ri * 8 + qc];
    const uint32_t ia1 = g_iext[(size_t)(ri + 8) * 8 + qc];
    const uint32_t ia2 = g_iext[(size_t)ri * 8 + qc + 4];
    const uint32_t ia3 = g_iext[(size_t)(ri + 8) * 8 + qc + 4];
    const float h0 = g_h[ri], h1 = g_h[ri + 8];

    float acc[8][4];
    #pragma unroll
    for (int nb = 0; nb < 8; nb++)
        #pragma unroll
        for (int q = 0; q < 4; q++) acc[nb][q] = 0.f;

    const int J_begin = jh * (N_PTS / 16 / JSPLIT);   // 64 J-blocks per slice
    const int J_end   = J_begin + (N_PTS / 16 / JSPLIT);

    // ---- pipeline prologue: A frags + B frags for J_begin ----
    uint32_t f0, f1, f2, f3;
    {
        float2 sfa = g_jext2[(size_t)(J_begin * 16 + qr) * 4 + qc];
        float2 sfb = g_jext2[(size_t)(J_begin * 16 + 8 + qr) * 4 + qc];
        float cA[4], cB[4];
        score_mma_h(cA, ia0, ia1, ia2, ia3, sfa, h0, h1);
        score_mma_h(cB, ia0, ia1, ia2, ia3, sfb, h0, h1);
        finalize(f0, f1, cA);
        finalize(f2, f3, cB);
    }
    const uint4* bp0 = g_Ufrag + (size_t)(J_begin * 4) * 32 + lane;
    uint4 bb0 = bp0[0], bb1 = bp0[32], bb2 = bp0[64], bb3 = bp0[96];

    // ---- steady loop: all iterations except the last ----
    #pragma unroll 2
    for (int J = J_begin; J < J_end - 1; ++J) {
        const int Jn = J + 1;   // unconditional (last iteration peeled)

        // 1) next-J score features + tf32 MMAs (h folded into C init)
        float2 nfa = g_jext2[(size_t)(Jn * 16 + qr) * 4 + qc];
        float2 nfb = g_jext2[(size_t)(Jn * 16 + 8 + qr) * 4 + qc];
        float cA[4], cB[4];
        score_mma_h(cA, ia0, ia1, ia2, ia3, nfa, h0, h1);
        score_mma_h(cB, ia0, ia1, ia2, ia3, nfb, h0, h1);

        // 2) current-J HMMAs (A/B frags ready since last iteration)
        HMMA(acc[0], f0, f1, f2, f3, bb0.x, bb0.y);
        HMMA(acc[1], f0, f1, f2, f3, bb0.z, bb0.w);
        HMMA(acc[2], f0, f1, f2, f3, bb1.x, bb1.y);
        HMMA(acc[3], f0, f1, f2, f3, bb1.z, bb1.w);
        HMMA(acc[4], f0, f1, f2, f3, bb2.x, bb2.y);
        HMMA(acc[5], f0, f1, f2, f3, bb2.z, bb2.w);
        HMMA(acc[6], f0, f1, f2, f3, bb3.x, bb3.y);
        HMMA(acc[7], f0, f1, f2, f3, bb3.z, bb3.w);

        // 3) prefetch next-J B fragments
        const uint4* np = g_Ufrag + (size_t)(Jn * 4) * 32 + lane;
        uint4 nb0 = np[0], nb1 = np[32], nb2 = np[64], nb3 = np[96];

        // 4) finalize next-J A fragments
        finalize(f0, f1, cA);
        finalize(f2, f3, cB);

        // 5) rotate B
        bb0 = nb0; bb1 = nb1; bb2 = nb2; bb3 = nb3;
    }

    // ---- peeled last iteration: HMMAs only ----
    HMMA(acc[0], f0, f1, f2, f3, bb0.x, bb0.y);
    HMMA(acc[1], f0, f1, f2, f3, bb0.z, bb0.w);
    HMMA(acc[2], f0, f1, f2, f3, bb1.x, bb1.y);
    HMMA(acc[3], f0, f1, f2, f3, bb1.z, bb1.w);
    HMMA(acc[4], f0, f1, f2, f3, bb2.x, bb2.y);
    HMMA(acc[5], f0, f1, f2, f3, bb2.z, bb2.w);
    HMMA(acc[6], f0, f1, f2, f3, bb3.x, bb3.y);
    HMMA(acc[7], f0, f1, f2, f3, bb3.z, bb3.w);

    // epilogue: write fp32 partials
    float* P = g_part + (size_t)jh * N_PTS * C_DIM;
    #pragma unroll
    for (int nb = 0; nb < 8; nb++) {
        const int col = nb * 8 + 2 * qc;
        *(float2*)(P + (size_t)ri * C_DIM + col)       = make_float2(acc[nb][0], acc[nb][1]);
        *(float2*)(P + (size_t)(ri + 8) * C_DIM + col) = make_float2(acc[nb][2], acc[nb][3]);
    }
}

// ---------------- merge: out = sum(partials) - U ----------------
__global__ void merge_kernel(const float* __restrict__ U, float* __restrict__ out) {
    int idx = blockIdx.x * blockDim.x + threadIdx.x;   // float4 index
    float4 u = ((const float4*)U)[idx];
    float4 o = make_float4(-u.x, -u.y, -u.z, -u.w);
    #pragma unroll
    for (int s = 0; s < JSPLIT; s++) {
        float4 p = ((const float4*)g_part)[idx + (size_t)s * (N_PTS * C_DIM / 4)];
        o.x += p.x; o.y += p.y; o.z += p.z; o.w += p.w;
    }
    ((float4*)out)[idx] = o;
}

extern "C" void kernel_launch(void* const* d_in, const int* in_sizes, int n_in,
                              void* d_out, int out_size) {
    const float* U   = (const float*)d_in[0];
    const float* ref = (const float*)d_in[1];
    if (n_in >= 2 && in_sizes[0] == N_PTS * 5) {  // defensive metadata-order check
        U = (const float*)d_in[1];
        ref = (const float*)d_in[0];
    }
    prep_all<<<NFRAG / 256, 256>>>(ref, U);
    lsh_main<<<256 * JSPLIT, 128>>>();
    merge_kernel<<<N_PTS * C_DIM / 4 / 256, 256>>>(U, (float*)d_out);
}

// round 16
// speedup vs baseline: 1.1567x; 1.1567x over previous
#include <cuda_runtime.h>
#include <cuda_fp16.h>
#include <cstdint>

#define N_PTS 16384
#define C_DIM 64
#define NFRAG (N_PTS / 16 * 4 * 32)   // 131072 uint4 fragments
#define JSPLIT 16

// ---------------- scratch (no allocs allowed) ----------------
__device__ uint32_t g_iext[N_PTS * 8];        // A-side feats [r0..r4,1,0,0] tf32 bits
__device__ float    g_h[N_PTS];               // exact fp32 h_i
__device__ float2   g_jext2[N_PTS * 4];       // score-mma B frags {(f0,f4),(f1,h),(f2,0),(f3,0)}
__device__ uint4    g_Ufrag[NFRAG];           // U fp16, HMMA-B fragment order
__device__ float    g_part[JSPLIT * N_PTS * C_DIM]; // split-j partials

__device__ __forceinline__ uint32_t tf32r(float v) {
    uint32_t u; asm("cvt.rna.tf32.f32 %0, %1;" : "=r"(u) : "f"(v)); return u;
}

// ---------------- fused prep: features + U fragments ----------------
__global__ void prep_all(const float* __restrict__ ref, const float* __restrict__ U) {
    int idx = blockIdx.x * blockDim.x + threadIdx.x;

    if (idx < N_PTS) {
        const int p = idx;
        const float L2E = 1.4426950408889634f;
        const float S   = 1.2011224087864498f;   // sqrt(log2 e)
        float r[5]; float sq = 0.f;
        #pragma unroll
        for (int c = 0; c < 5; c++) { r[c] = ref[p * 5 + c]; sq += r[c] * r[c]; }
        float h = -0.5f * L2E * sq;
        uint32_t f[6];
        #pragma unroll
        for (int c = 0; c < 5; c++) f[c] = tf32r(r[c] * S);
        f[5] = tf32r(h);
        uint32_t* ie = g_iext + (size_t)p * 8;
        ie[0] = f[0]; ie[1] = f[1]; ie[2] = f[2]; ie[3] = f[3]; ie[4] = f[4];
        ie[5] = tf32r(1.0f); ie[6] = 0u; ie[7] = 0u;
        g_h[p] = h;
        float2* je = g_jext2 + (size_t)p * 4;
        je[0] = make_float2(__uint_as_float(f[0]), __uint_as_float(f[4]));
        je[1] = make_float2(__uint_as_float(f[1]), __uint_as_float(f[5]));
        je[2] = make_float2(__uint_as_float(f[2]), 0.f);
        je[3] = make_float2(__uint_as_float(f[3]), 0.f);
    }

    if (idx < NFRAG) {
        int lane = idx & 31, nbp = (idx >> 5) & 3, J = idx >> 7;
        int qr = lane >> 2, qc = lane & 3;
        int j = J * 16 + 2 * qc;
        uint32_t rr[4];
        #pragma unroll
        for (int p = 0; p < 2; p++) {
            int c = (2 * nbp + p) * 8 + qr;
            float f0 = U[(size_t)j * C_DIM + c];
            float f1 = U[(size_t)(j + 1) * C_DIM + c];
            float f2 = U[(size_t)(j + 8) * C_DIM + c];
            float f3 = U[(size_t)(j + 9) * C_DIM + c];
            __half2 h0 = __floats2half2_rn(f0, f1);   // lo = row 2qc
            __half2 h1 = __floats2half2_rn(f2, f3);
            rr[2 * p]     = *(uint32_t*)&h0;
            rr[2 * p + 1] = *(uint32_t*)&h1;
        }
        g_Ufrag[idx] = make_uint4(rr[0], rr[1], rr[2], rr[3]);
    }
}

// ---------------- main kernel pieces ----------------
__device__ __forceinline__ void score_mma(
    float c[4],
    uint32_t ia0, uint32_t ia1, uint32_t ia2, uint32_t ia3, float2 bf)
{
    uint32_t b0 = __float_as_uint(bf.x), b1 = __float_as_uint(bf.y);
    c[0] = 0.f; c[1] = 0.f; c[2] = 0.f; c[3] = 0.f;
    asm volatile("mma.sync.aligned.m16n8k8.row.col.f32.tf32.tf32.f32 "
                 "{%0,%1,%2,%3}, {%4,%5,%6,%7}, {%8,%9}, {%0,%1,%2,%3};"
                 : "+f"(c[0]), "+f"(c[1]), "+f"(c[2]), "+f"(c[3])
                 : "r"(ia0), "r"(ia1), "r"(ia2), "r"(ia3), "r"(b0), "r"(b1));
}

__device__ __forceinline__ void finalize(
    uint32_t& w_lo, uint32_t& w_hi, const float c[4], float h0, float h1)
{
    float e0 = c[0] + h0, e1 = c[1] + h0, e2 = c[2] + h1, e3 = c[3] + h1;
    uint32_t plo, phi;
    asm("cvt.rn.f16x2.f32 %0, %1, %2;" : "=r"(plo) : "f"(e1), "f"(e0)); // lo=e0
    asm("cvt.rn.f16x2.f32 %0, %1, %2;" : "=r"(phi) : "f"(e3), "f"(e2));
    asm("min.f16x2 %0, %1, %2;" : "=r"(plo) : "r"(plo), "r"(0u));
    asm("min.f16x2 %0, %1, %2;" : "=r"(phi) : "r"(phi), "r"(0u));
    asm("ex2.approx.f16x2 %0, %1;" : "=r"(w_lo) : "r"(plo));
    asm("ex2.approx.f16x2 %0, %1;" : "=r"(w_hi) : "r"(phi));
}

#define HMMA(ACC, A0, A1, A2, A3, B0, B1) \
    asm volatile("mma.sync.aligned.m16n8k16.row.col.f32.f16.f16.f32 " \
                 "{%0,%1,%2,%3}, {%4,%5,%6,%7}, {%8,%9}, {%0,%1,%2,%3};" \
                 : "+f"(ACC[0]), "+f"(ACC[1]), "+f"(ACC[2]), "+f"(ACC[3]) \
                 : "r"(A0), "r"(A1), "r"(A2), "r"(A3), "r"(B0), "r"(B1))

__global__ void __launch_bounds__(128, 4)
lsh_main(void) {
    const int lane = threadIdx.x & 31;
    const int w    = threadIdx.x >> 5;          // 0..3: m32 slice within 128-row i-tile
    const int bid  = blockIdx.x;
    const int ib   = bid & 127;                 // i-tile (128 rows)
    const int jh   = bid >> 7;                  // j-slice 0..15
    const int i0   = ib * 128;
    const int qr   = lane >> 2, qc = lane & 3;

    // two m16 tiles per warp: Upper rows riU(+8), Lower riL(+8)
    const int riU = i0 + w * 32 + qr;
    const int riL = riU + 16;
    const uint32_t iaU0 = g_iext[(size_t)riU * 8 + qc];
    const uint32_t iaU1 = g_iext[(size_t)(riU + 8) * 8 + qc];
    const uint32_t iaU2 = g_iext[(size_t)riU * 8 + qc + 4];
    const uint32_t iaU3 = g_iext[(size_t)(riU + 8) * 8 + qc + 4];
    const uint32_t iaL0 = g_iext[(size_t)riL * 8 + qc];
    const uint32_t iaL1 = g_iext[(size_t)(riL + 8) * 8 + qc];
    const uint32_t iaL2 = g_iext[(size_t)riL * 8 + qc + 4];
    const uint32_t iaL3 = g_iext[(size_t)(riL + 8) * 8 + qc + 4];
    const float hU0 = g_h[riU], hU1 = g_h[riU + 8];
    const float hL0 = g_h[riL], hL1 = g_h[riL + 8];

    float aU[8][4], aL[8][4];
    #pragma unroll
    for (int nb = 0; nb < 8; nb++)
        #pragma unroll
        for (int q = 0; q < 4; q++) { aU[nb][q] = 0.f; aL[nb][q] = 0.f; }

    const int J_begin = jh * (N_PTS / 16 / JSPLIT);   // 64 J-blocks per slice
    const int J_end   = J_begin + (N_PTS / 16 / JSPLIT);

    // ---- pipeline prologue: A frags + B frags for J_begin ----
    uint32_t fU0, fU1, fU2, fU3, fL0, fL1, fL2, fL3;
    {
        float2 sfa = g_jext2[(size_t)(J_begin * 16 + qr) * 4 + qc];
        float2 sfb = g_jext2[(size_t)(J_begin * 16 + 8 + qr) * 4 + qc];
        float cUa[4], cUb[4], cLa[4], cLb[4];
        score_mma(cUa, iaU0, iaU1, iaU2, iaU3, sfa);
        score_mma(cUb, iaU0, iaU1, iaU2, iaU3, sfb);
        score_mma(cLa, iaL0, iaL1, iaL2, iaL3, sfa);
        score_mma(cLb, iaL0, iaL1, iaL2, iaL3, sfb);
        finalize(fU0, fU1, cUa, hU0, hU1);
        finalize(fU2, fU3, cUb, hU0, hU1);
        finalize(fL0, fL1, cLa, hL0, hL1);
        finalize(fL2, fL3, cLb, hL0, hL1);
    }
    const uint4* bp0 = g_Ufrag + (size_t)(J_begin * 4) * 32 + lane;
    uint4 bb0 = bp0[0], bb1 = bp0[32], bb2 = bp0[64], bb3 = bp0[96];

    #pragma unroll 2
    for (int J = J_begin; J < J_end; ++J) {
        const int Jn = (J + 1 < J_end) ? (J + 1) : J;   // clamp; last-iter result unused

        // 1) next-J score features + tf32 MMAs (results needed only after HMMAs)
        float2 nfa = g_jext2[(size_t)(Jn * 16 + qr) * 4 + qc];
        float2 nfb = g_jext2[(size_t)(Jn * 16 + 8 + qr) * 4 + qc];
        float cUa[4], cUb[4], cLa[4], cLb[4];
        score_mma(cUa, iaU0, iaU1, iaU2, iaU3, nfa);
        score_mma(cUb, iaU0, iaU1, iaU2, iaU3, nfb);
        score_mma(cLa, iaL0, iaL1, iaL2, iaL3, nfa);
        score_mma(cLb, iaL0, iaL1, iaL2, iaL3, nfb);

        // 2) current-J HMMAs (A/B frags ready since last iteration)
        HMMA(aU[0], fU0, fU1, fU2, fU3, bb0.x, bb0.y);
        HMMA(aU[1], fU0, fU1, fU2, fU3, bb0.z, bb0.w);
        HMMA(aL[0], fL0, fL1, fL2, fL3, bb0.x, bb0.y);
        HMMA(aL[1], fL0, fL1, fL2, fL3, bb0.z, bb0.w);
        HMMA(aU[2], fU0, fU1, fU2, fU3, bb1.x, bb1.y);
        HMMA(aU[3], fU0, fU1, fU2, fU3, bb1.z, bb1.w);
        HMMA(aL[2], fL0, fL1, fL2, fL3, bb1.x, bb1.y);
        HMMA(aL[3], fL0, fL1, fL2, fL3, bb1.z, bb1.w);
        HMMA(aU[4], fU0, fU1, fU2, fU3, bb2.x, bb2.y);
        HMMA(aU[5], fU0, fU1, fU2, fU3, bb2.z, bb2.w);
        HMMA(aL[4], fL0, fL1, fL2, fL3, bb2.x, bb2.y);
        HMMA(aL[5], fL0, fL1, fL2, fL3, bb2.z, bb2.w);
        HMMA(aU[6], fU0, fU1, fU2, fU3, bb3.x, bb3.y);
        HMMA(aU[7], fU0, fU1, fU2, fU3, bb3.z, bb3.w);
        HMMA(aL[6], fL0, fL1, fL2, fL3, bb3.x, bb3.y);
        HMMA(aL[7], fL0, fL1, fL2, fL3, bb3.z, bb3.w);

        // 3) prefetch next-J B fragments
        const uint4* np = g_Ufrag + (size_t)(Jn * 4) * 32 + lane;
        uint4 nb0 = np[0], nb1 = np[32], nb2 = np[64], nb3 = np[96];

        // 4) finalize next-J A fragments (tf32 results drained behind HMMA block)
        finalize(fU0, fU1, cUa, hU0, hU1);
        finalize(fU2, fU3, cUb, hU0, hU1);
        finalize(fL0, fL1, cLa, hL0, hL1);
        finalize(fL2, fL3, cLb, hL0, hL1);

        // 5) rotate B
        bb0 = nb0; bb1 = nb1; bb2 = nb2; bb3 = nb3;
    }

    // epilogue: write fp32 partials
    float* P = g_part + (size_t)jh * N_PTS * C_DIM;
    #pragma unroll
    for (int nb = 0; nb < 8; nb++) {
        const int col = nb * 8 + 2 * qc;
        *(float2*)(P + (size_t)riU * C_DIM + col)       = make_float2(aU[nb][0], aU[nb][1]);
        *(float2*)(P + (size_t)(riU + 8) * C_DIM + col) = make_float2(aU[nb][2], aU[nb][3]);
        *(float2*)(P + (size_t)riL * C_DIM + col)       = make_float2(aL[nb][0], aL[nb][1]);
        *(float2*)(P + (size_t)(riL + 8) * C_DIM + col) = make_float2(aL[nb][2], aL[nb][3]);
    }
}

// ---------------- merge: out = sum(partials) - U ----------------
__global__ void merge_kernel(const float* __restrict__ U, float* __restrict__ out) {
    int idx = blockIdx.x * blockDim.x + threadIdx.x;   // float4 index
    float4 u = ((const float4*)U)[idx];
    float4 o = make_float4(-u.x, -u.y, -u.z, -u.w);
    #pragma unroll
    for (int s = 0; s < JSPLIT; s++) {
        float4 p = ((const float4*)g_part)[idx + (size_t)s * (N_PTS * C_DIM / 4)];
        o.x += p.x; o.y += p.y; o.z += p.z; o.w += p.w;
    }
    ((float4*)out)[idx] = o;
}

extern "C" void kernel_launch(void* const* d_in, const int* in_sizes, int n_in,
                              void* d_out, int out_size) {
    const float* U   = (const float*)d_in[0];
    const float* ref = (const float*)d_in[1];
    if (n_in >= 2 && in_sizes[0] == N_PTS * 5) {  // defensive metadata-order check
        U = (const float*)d_in[1];
        ref = (const float*)d_in[0];
    }
    prep_all<<<NFRAG / 256, 256>>>(ref, U);
    lsh_main<<<128 * JSPLIT, 128>>>();
    merge_kernel<<<N_PTS * C_DIM / 4 / 256, 256>>>(U, (float*)d_out);
}